// round 2
// baseline (speedup 1.0000x reference)
#include <cuda_runtime.h>
#include <cstdint>
#include <cstddef>

// ---------------- problem dims ----------------
static constexpr int Mdim = 8192;   // B*T
static constexpr int Ndim = 1024;   // codebook rows
static constexpr int Kdim = 512;    // D

// ---------------- tiling ----------------
static constexpr int MT = 128;
static constexpr int NT = 128;
static constexpr int KC = 32;            // K floats per chunk (128B rows)
static constexpr int NCHUNK = Kdim / KC; // 16
static constexpr int THREADS = 256;      // 8 warps: 4 (M) x 2 (N)
static constexpr int STAGES = 3;
static constexpr int STAGE_BYTES = 32768;          // A 16K | B 16K
static constexpr int SM_TOTAL = STAGES * STAGE_BYTES; // 96 KB

__device__ float g_xsq[Mdim];
__device__ float g_csq[Ndim];

// ---------------- helpers ----------------
__device__ __forceinline__ uint32_t smem_u32(const void* p) {
    uint32_t a;
    asm("{ .reg .u64 t; cvta.to.shared.u64 t, %1; cvt.u32.u64 %0, t; }"
        : "=r"(a) : "l"(p));
    return a;
}
#define SW128(o) ((o) ^ (((o) >> 3) & 0x70))

__device__ __forceinline__ void cp16(uint32_t dst, const void* src) {
    asm volatile("cp.async.cg.shared.global [%0], [%1], 16;"
                 :: "r"(dst), "l"(src) : "memory");
}
#define CP_COMMIT() asm volatile("cp.async.commit_group;" ::: "memory")
#define CP_WAIT(n)  asm volatile("cp.async.wait_group %0;" :: "n"(n) : "memory")

__device__ __forceinline__ void ldsm_x4(uint32_t& r0, uint32_t& r1,
                                        uint32_t& r2, uint32_t& r3,
                                        uint32_t addr) {
    asm volatile("ldmatrix.sync.aligned.m8n8.x4.shared.b16 {%0,%1,%2,%3}, [%4];"
                 : "=r"(r0), "=r"(r1), "=r"(r2), "=r"(r3) : "r"(addr));
}

__device__ __forceinline__ void mma_tf32(float* c, const uint32_t* a,
                                         uint32_t b0, uint32_t b1) {
    asm volatile(
        "mma.sync.aligned.m16n8k8.row.col.f32.tf32.tf32.f32 "
        "{%0,%1,%2,%3}, {%4,%5,%6,%7}, {%8,%9}, {%0,%1,%2,%3};"
        : "+f"(c[0]), "+f"(c[1]), "+f"(c[2]), "+f"(c[3])
        : "r"(a[0]), "r"(a[1]), "r"(a[2]), "r"(a[3]), "r"(b0), "r"(b1));
}

// ---------------- precompute ||x||^2, ||c||^2 ----------------
__global__ void __launch_bounds__(256) rowsq_kernel(const float* __restrict__ x,
                                                    const float* __restrict__ cb) {
    int row  = blockIdx.x * 8 + (threadIdx.x >> 5);
    int lane = threadIdx.x & 31;
    const float4* src;
    float* dst;
    if (row < Mdim) {
        src = reinterpret_cast<const float4*>(x) + (size_t)row * (Kdim / 4);
        dst = g_xsq + row;
    } else if (row < Mdim + Ndim) {
        int r = row - Mdim;
        src = reinterpret_cast<const float4*>(cb) + (size_t)r * (Kdim / 4);
        dst = g_csq + r;
    } else return;
    float s = 0.f;
    #pragma unroll
    for (int i = lane; i < Kdim / 4; i += 32) {
        float4 v = src[i];
        s += v.x * v.x + v.y * v.y + v.z * v.z + v.w * v.w;
    }
    #pragma unroll
    for (int o = 16; o; o >>= 1) s += __shfl_xor_sync(0xffffffffu, s, o);
    if (lane == 0) *dst = s;
}

// ---------------- chunk loader: 128x32f A + 128x32f B, SW128 ----------------
__device__ __forceinline__ void load_chunk(const float* __restrict__ x,
                                           const float* __restrict__ cb,
                                           int m0, int n0, int c,
                                           uint32_t stg, int tid) {
    const float* xa  = x  + (size_t)m0 * Kdim + c * KC;
    const float* cbp = cb + (size_t)n0 * Kdim + c * KC;
    #pragma unroll
    for (int t = 0; t < 4; t++) {
        int i  = tid + t * THREADS;   // 0..1023
        int r  = i >> 3;              // row 0..127
        int j4 = i & 7;               // 16B piece within 128B row
        uint32_t off = SW128((uint32_t)(r * 128 + j4 * 16));
        cp16(stg + off,          xa  + (size_t)r * Kdim + j4 * 4);
        cp16(stg + 16384u + off, cbp + (size_t)r * Kdim + j4 * 4);
    }
}

// ---------------- GEMM + fused epilogue ----------------
__global__ void __launch_bounds__(THREADS, 2)
gemm_kernel(const float* __restrict__ x, const float* __restrict__ cb,
            const float* __restrict__ precision, float* __restrict__ out) {
    extern __shared__ char smem[];
    const uint32_t sb = smem_u32(smem);
    const int tid  = threadIdx.x;
    const int lane = tid & 31;
    const int w    = tid >> 5;
    const int wm   = w >> 1;          // 0..3
    const int wn   = w & 1;           // 0..1
    const int m0 = blockIdx.y * MT;
    const int n0 = blockIdx.x * NT;

    // ldmatrix per-thread base offsets (bytes, pre-swizzle)
    // A: mf blocks at rows wm*32 + mf*16 + (lane&15), col16 = lane>=16
    int aRow[2], aColB;
    aRow[0] = wm * 32 + (lane & 15);
    aRow[1] = aRow[0] + 16;
    aColB   = ((lane >> 4) & 1) * 16;
    // B: nf2 blocks at rows wn*64 + nf2*16 + (lane&7) + ((lane>>4)&1)*8,
    //    col16 = (lane>>3)&1
    int bRowBase = wn * 64 + (lane & 7) + ((lane >> 4) & 1) * 8;
    int bColB    = ((lane >> 3) & 1) * 16;

    float acc[2][8][4];
    #pragma unroll
    for (int mf = 0; mf < 2; mf++)
        #pragma unroll
        for (int nf = 0; nf < 8; nf++)
            #pragma unroll
            for (int q = 0; q < 4; q++) acc[mf][nf][q] = 0.f;

    // prologue
    load_chunk(x, cb, m0, n0, 0, sb + 0 * STAGE_BYTES, tid); CP_COMMIT();
    load_chunk(x, cb, m0, n0, 1, sb + 1 * STAGE_BYTES, tid); CP_COMMIT();

    #pragma unroll 1
    for (int c = 0; c < NCHUNK; c++) {
        if (c < NCHUNK - 1) { CP_WAIT(1); } else { CP_WAIT(0); }
        __syncthreads();
        // prefetch chunk c+2 (stage reuse is safe: all warps finished c-1)
        if (c + 2 < NCHUNK) {
            load_chunk(x, cb, m0, n0, c + 2, sb + ((c + 2) % 3) * STAGE_BYTES, tid);
            CP_COMMIT();
        }
        const uint32_t sA = sb + (c % 3) * STAGE_BYTES;
        const uint32_t sB = sA + 16384u;
        #pragma unroll
        for (int ks = 0; ks < 4; ks++) {
            uint32_t af[2][4];
            #pragma unroll
            for (int mf = 0; mf < 2; mf++) {
                uint32_t off = (uint32_t)(aRow[mf] * 128 + ks * 32 + aColB);
                ldsm_x4(af[mf][0], af[mf][1], af[mf][2], af[mf][3],
                        sA + SW128(off));
            }
            uint32_t bf[4][4];
            #pragma unroll
            for (int nf2 = 0; nf2 < 4; nf2++) {
                uint32_t off = (uint32_t)((bRowBase + nf2 * 16) * 128
                                          + ks * 32 + bColB);
                ldsm_x4(bf[nf2][0], bf[nf2][1], bf[nf2][2], bf[nf2][3],
                        sB + SW128(off));
            }
            #pragma unroll
            for (int mf = 0; mf < 2; mf++)
                #pragma unroll
                for (int nf = 0; nf < 8; nf++)
                    mma_tf32(acc[mf][nf], af[mf],
                             bf[nf >> 1][(nf & 1) * 2],
                             bf[nf >> 1][(nf & 1) * 2 + 1]);
        }
    }

    // ---------------- epilogue ----------------
    __syncthreads();   // everyone done reading stage smem
    float* sE = reinterpret_cast<float*>(smem);   // [128][132] staging
    const int erow = wm * 32 + (lane >> 2);
    const int ecol = wn * 64 + (lane & 3) * 2;
    #pragma unroll
    for (int mf = 0; mf < 2; mf++) {
        #pragma unroll
        for (int nf = 0; nf < 8; nf++) {
            float2* p0 = reinterpret_cast<float2*>(
                &sE[(erow + mf * 16) * 132 + ecol + nf * 8]);
            float2* p1 = reinterpret_cast<float2*>(
                &sE[(erow + mf * 16 + 8) * 132 + ecol + nf * 8]);
            *p0 = make_float2(acc[mf][nf][0], acc[mf][nf][1]);
            *p1 = make_float2(acc[mf][nf][2], acc[mf][nf][3]);
        }
    }
    __syncthreads();

    const float prec = precision[0];
    const int cj = (tid & 31) * 4;              // col group of 4
    const float4 cs = *reinterpret_cast<const float4*>(&g_csq[n0 + cj]);
    #pragma unroll 1
    for (int it = 0; it < 16; it++) {
        const int r = (tid >> 5) + it * 8;      // 0..127
        const float xs = g_xsq[m0 + r];
        const float* sp = &sE[r * 132 + cj];
        float4 v;
        v.x = prec * (2.f * sp[0] - xs - cs.x);
        v.y = prec * (2.f * sp[1] - xs - cs.y);
        v.z = prec * (2.f * sp[2] - xs - cs.z);
        v.w = prec * (2.f * sp[3] - xs - cs.w);
        *reinterpret_cast<float4*>(&out[(size_t)(m0 + r) * Ndim + n0 + cj]) = v;
    }
}

// ---------------- launch ----------------
extern "C" void kernel_launch(void* const* d_in, const int* in_sizes, int n_in,
                              void* d_out, int out_size) {
    (void)in_sizes; (void)n_in; (void)out_size;
    const float* x    = (const float*)d_in[0];
    const float* cb   = (const float*)d_in[1];
    const float* prec = (const float*)d_in[2];
    float* out = (float*)d_out;

    cudaFuncSetAttribute(gemm_kernel,
                         cudaFuncAttributeMaxDynamicSharedMemorySize, SM_TOTAL);

    rowsq_kernel<<<(Mdim + Ndim) / 8, 256>>>(x, cb);
    dim3 grid(Ndim / NT, Mdim / MT);   // (8, 64) = 512 CTAs
    gemm_kernel<<<grid, THREADS, SM_TOTAL>>>(x, cb, prec, out);
}